// round 3
// baseline (speedup 1.0000x reference)
#include <cuda_runtime.h>

#define W 512
#define PLANE (512*512)
#define NPLANES 32
#define HALF 16
#define TOTAL (NPLANES*PLANE)
#define IMG_ELEMS (HALF*PLANE)   // 4,194,304 per input tensor
#define TS 64
#define NT 256
#define RED_BLOCKS 2048
#define N_ITER 20

// Scratch: device globals (no allocation allowed).
__device__ float g_bufA[TOTAL];
__device__ float g_bufB[TOTAL];
__device__ float g_skel[TOTAL];
__device__ float g_part[RED_BLOCKS * 8];

__device__ __forceinline__ float gelu_exact(float x) {
    // torch F.gelu default: 0.5*x*(1+erf(x/sqrt(2)))
    return 0.5f * x * (1.0f + erff(x * 0.70710678118654752f));
}

// ---------------------------------------------------------------------------
// INIT: skel = gelu(img - dilate(erode(img))); bufA = img
// Halo 2. Planes 0..15 = y_pred, 16..31 = y_true.
// ---------------------------------------------------------------------------
__global__ __launch_bounds__(NT) void init_kernel(const float* __restrict__ y_true,
                                                  const float* __restrict__ y_pred) {
    __shared__ float s_img[68 * 69];   // tile + halo2, pitch 69
    __shared__ float s_e1[66 * 67];    // erode(img) on T+1, pitch 67

    const int plane = blockIdx.z;
    const float* src = ((plane < HALF) ? y_pred : y_true) + (plane & 15) * PLANE;
    const int by = blockIdx.y * TS, bx = blockIdx.x * TS;
    const int tid = threadIdx.x;
    const float BIG = 1e30f;

    // Load img with halo 2; out-of-image -> +BIG (erode pads +inf)
    for (int i = tid; i < 68 * 68; i += NT) {
        int r = i / 68, c = i - r * 68;
        int gr = by + r - 2, gc = bx + c - 2;
        float v = BIG;
        if ((unsigned)gr < 512u && (unsigned)gc < 512u) v = src[gr * W + gc];
        s_img[r * 69 + c] = v;
    }
    __syncthreads();

    // E1 = erode(img) on T+1; out-of-image -> -BIG (feeds dilate, pads -inf)
    for (int i = tid; i < 66 * 66; i += NT) {
        int r = i / 66, c = i - r * 66;
        int gr = by + r - 1, gc = bx + c - 1;
        float v = -BIG;
        if ((unsigned)gr < 512u && (unsigned)gc < 512u) {
            int rr = r + 1, cc = c + 1;
            float ce = s_img[rr * 69 + cc];
            v = fminf(ce, fminf(fminf(s_img[(rr - 1) * 69 + cc], s_img[(rr + 1) * 69 + cc]),
                                fminf(s_img[rr * 69 + cc - 1], s_img[rr * 69 + cc + 1])));
        }
        s_e1[r * 67 + c] = v;
    }
    __syncthreads();

    // open = dilate(E1); skel = gelu(img - open); bufA = img
    for (int i = tid; i < TS * TS; i += NT) {
        int r = i >> 6, c = i & 63;
        float m = -BIG;
        #pragma unroll
        for (int dr = 0; dr < 3; dr++)
            #pragma unroll
            for (int dc = 0; dc < 3; dc++)
                m = fmaxf(m, s_e1[(r + dr) * 67 + c + dc]);
        float img = s_img[(r + 2) * 69 + (c + 2)];
        int g = plane * PLANE + (by + r) * W + (bx + c);
        g_skel[g] = gelu_exact(img - m);
        g_bufA[g] = img;
    }
}

// ---------------------------------------------------------------------------
// STEP: img' = erode(img); delta = gelu(img' - dilate(erode(img')));
//       skel += gelu(delta - skel*delta)
// Halo 3. E2 reuses s_img storage (keeps static smem under 48 KB).
// ---------------------------------------------------------------------------
__global__ __launch_bounds__(NT) void step_kernel(int readA) {
    __shared__ float s_img[70 * 71];   // tile + halo3, pitch 71; later reused as E2 (pitch 67)
    __shared__ float s_e1[68 * 69];    // erode(img) on T+2, pitch 69

    const float* src = readA ? g_bufA : g_bufB;
    float*       dst = readA ? g_bufB : g_bufA;
    const int plane = blockIdx.z;
    const float* sp = src + plane * PLANE;
    const int by = blockIdx.y * TS, bx = blockIdx.x * TS;
    const int tid = threadIdx.x;
    const float BIG = 1e30f;

    // Load img with halo 3; out-of-image -> +BIG
    for (int i = tid; i < 70 * 70; i += NT) {
        int r = i / 70, c = i - r * 70;
        int gr = by + r - 3, gc = bx + c - 3;
        float v = BIG;
        if ((unsigned)gr < 512u && (unsigned)gc < 512u) v = sp[gr * W + gc];
        s_img[r * 71 + c] = v;
    }
    __syncthreads();

    // E1 = erode(img) on T+2; out-of-image -> +BIG (feeds second erode)
    for (int i = tid; i < 68 * 68; i += NT) {
        int r = i / 68, c = i - r * 68;
        int gr = by + r - 2, gc = bx + c - 2;
        float v = BIG;
        if ((unsigned)gr < 512u && (unsigned)gc < 512u) {
            int rr = r + 1, cc = c + 1;
            float ce = s_img[rr * 71 + cc];
            v = fminf(ce, fminf(fminf(s_img[(rr - 1) * 71 + cc], s_img[(rr + 1) * 71 + cc]),
                                fminf(s_img[rr * 71 + cc - 1], s_img[rr * 71 + cc + 1])));
        }
        s_e1[r * 69 + c] = v;
    }
    __syncthreads();

    // E2 = erode(E1) on T+1; out-of-image -> -BIG (feeds dilate).
    // Stored into s_img (pitch 67) — s_img contents no longer needed.
    for (int i = tid; i < 66 * 66; i += NT) {
        int r = i / 66, c = i - r * 66;
        int gr = by + r - 1, gc = bx + c - 1;
        float v = -BIG;
        if ((unsigned)gr < 512u && (unsigned)gc < 512u) {
            int rr = r + 1, cc = c + 1;
            float ce = s_e1[rr * 69 + cc];
            v = fminf(ce, fminf(fminf(s_e1[(rr - 1) * 69 + cc], s_e1[(rr + 1) * 69 + cc]),
                                fminf(s_e1[rr * 69 + cc - 1], s_e1[rr * 69 + cc + 1])));
        }
        s_img[r * 67 + c] = v;
    }
    __syncthreads();

    // open = dilate(E2); delta; skel update; write img' = E1(center)
    for (int i = tid; i < TS * TS; i += NT) {
        int r = i >> 6, c = i & 63;
        float m = -BIG;
        #pragma unroll
        for (int dr = 0; dr < 3; dr++)
            #pragma unroll
            for (int dc = 0; dc < 3; dc++)
                m = fmaxf(m, s_img[(r + dr) * 67 + c + dc]);
        float e1c = s_e1[(r + 2) * 69 + (c + 2)];
        float delta = gelu_exact(e1c - m);
        int g = plane * PLANE + (by + r) * W + (bx + c);
        float sk = g_skel[g];
        sk += gelu_exact(delta - sk * delta);
        g_skel[g] = sk;
        dst[g] = e1c;
    }
}

// ---------------------------------------------------------------------------
// Reductions (deterministic two-stage tree)
// ---------------------------------------------------------------------------
__device__ __forceinline__ float warpSum(float v) {
    #pragma unroll
    for (int o = 16; o; o >>= 1) v += __shfl_down_sync(0xffffffffu, v, o);
    return v;
}

__global__ __launch_bounds__(256) void reduce_kernel(const float* __restrict__ yt,
                                                     const float* __restrict__ yp) {
    float a[7] = {0.f, 0.f, 0.f, 0.f, 0.f, 0.f, 0.f};
    const int stride = gridDim.x * blockDim.x;
    for (int i = blockIdx.x * blockDim.x + threadIdx.x; i < IMG_ELEMS; i += stride) {
        float t = yt[i], p = yp[i];
        float sp = g_skel[i];               // skel_pred (planes 0..15)
        float st = g_skel[i + IMG_ELEMS];   // skel_true (planes 16..31)
        a[0] += t;       a[1] += p;       a[2] += t * p;
        a[3] += sp;      a[4] += sp * t;
        a[5] += st;      a[6] += st * p;
    }
    __shared__ float shm[8][8];
    const int lane = threadIdx.x & 31, wrp = threadIdx.x >> 5;
    #pragma unroll
    for (int j = 0; j < 7; j++) {
        float v = warpSum(a[j]);
        if (lane == 0) shm[wrp][j] = v;
    }
    __syncthreads();
    if (wrp == 0) {
        #pragma unroll
        for (int j = 0; j < 7; j++) {
            float v = (lane < 8) ? shm[lane][j] : 0.f;
            v = warpSum(v);
            if (lane == 0) g_part[blockIdx.x * 8 + j] = v;
        }
    }
}

__global__ __launch_bounds__(256) void final_kernel(float* __restrict__ out) {
    float a[7] = {0.f, 0.f, 0.f, 0.f, 0.f, 0.f, 0.f};
    for (int b = threadIdx.x; b < RED_BLOCKS; b += 256) {
        #pragma unroll
        for (int j = 0; j < 7; j++) a[j] += g_part[b * 8 + j];
    }
    __shared__ float shm[8][8];
    const int lane = threadIdx.x & 31, wrp = threadIdx.x >> 5;
    #pragma unroll
    for (int j = 0; j < 7; j++) {
        float v = warpSum(a[j]);
        if (lane == 0) shm[wrp][j] = v;
    }
    __syncthreads();
    if (wrp == 0) {
        float res[7];
        #pragma unroll
        for (int j = 0; j < 7; j++) {
            float v = (lane < 8) ? shm[lane][j] : 0.f;
            res[j] = warpSum(v);
        }
        if (lane == 0) {
            float S_t  = res[0];  // sum(y_true)
            float S_p  = res[1];  // sum(y_pred)
            float S_tp = res[2];  // sum(y_true*y_pred)
            float S_sp = res[3];  // sum(skel_pred)
            float S_spt= res[4];  // sum(skel_pred*y_true)
            float S_st = res[5];  // sum(skel_true)
            float S_stp= res[6];  // sum(skel_true*y_pred)
            float dice  = 1.0f - (2.0f * S_tp + 1.0f) / (S_t + S_p + 1.0f);
            float tprec = (S_spt + 1.0f) / (S_sp + 1.0f);
            float tsens = (S_stp + 1.0f) / (S_st + 1.0f);
            float cl    = 1.0f - 2.0f * (tprec * tsens) / (tprec + tsens);
            out[0] = 0.7f * dice + 0.3f * cl;
        }
    }
}

// ---------------------------------------------------------------------------
extern "C" void kernel_launch(void* const* d_in, const int* in_sizes, int n_in,
                              void* d_out, int out_size) {
    const float* y_true = (const float*)d_in[0];
    const float* y_pred = (const float*)d_in[1];

    dim3 grid(W / TS, W / TS, NPLANES);  // 8 x 8 x 32 = 2048 blocks
    dim3 blk(NT);

    init_kernel<<<grid, blk>>>(y_true, y_pred);
    for (int s = 0; s < N_ITER; ++s)
        step_kernel<<<grid, blk>>>((s & 1) == 0 ? 1 : 0);

    reduce_kernel<<<RED_BLOCKS, 256>>>(y_true, y_pred);
    final_kernel<<<1, 256>>>((float*)d_out);
}